// round 7
// baseline (speedup 1.0000x reference)
#include <cuda_runtime.h>

#define IMG_W 512
#define IMG_H 512
#define NBATCH 32
#define RSTRIP 16
#define BLOCK 256
// threads: 32 batches * (512/16 y-strips) * (512/4 x-strips) = 131072
#define TOTAL_THREADS (NBATCH * (IMG_H / RSTRIP) * (IMG_W / 4))
#define NBLOCKS (TOTAL_THREADS / BLOCK)   // 512
#define NPIX ((long long)NBATCH * IMG_H * IMG_W)

__device__ float2 g_partials[NBLOCKS];

struct RowF { float dh[4]; float sh[4]; };

__device__ __forceinline__ void load_row(const float* __restrict__ img, int y, int x0,
                                         float v[6]) {
    if ((unsigned)y < IMG_H) {
        const float* row = img + (size_t)y * IMG_W;
        float4 m = __ldg(reinterpret_cast<const float4*>(row + x0));
        v[1] = m.x; v[2] = m.y; v[3] = m.z; v[4] = m.w;
        v[0] = (x0 > 0)             ? __ldg(row + x0 - 1) : 0.f;
        v[5] = (x0 + 4 < IMG_W)     ? __ldg(row + x0 + 4) : 0.f;
    } else {
#pragma unroll
        for (int k = 0; k < 6; ++k) v[k] = 0.f;
    }
}

__device__ __forceinline__ void make_row(const float v[6], RowF& r) {
#pragma unroll
    for (int j = 0; j < 4; ++j) {
        r.dh[j] = v[j + 2] - v[j];                       // horizontal [-1,0,1]
        r.sh[j] = v[j] + 2.f * v[j + 1] + v[j + 2];      // horizontal [1,2,1]
    }
}

__global__ __launch_bounds__(BLOCK)
void fuse_main(const float* __restrict__ A, const float* __restrict__ Bi,
               const float* __restrict__ F, const int* __restrict__ scheme) {
    int t   = blockIdx.x * BLOCK + threadIdx.x;
    int b   = t >> 12;          // / 4096 strips per image
    int rem = t & 4095;
    int ys  = rem >> 7;         // 32 y-strips
    int xs  = rem & 127;        // 128 x-strips
    int x0  = xs << 2;
    int y0  = ys * RSTRIP;

    size_t off = (size_t)b * IMG_H * IMG_W;
    const float* pA = A  + off;
    const float* pB = Bi + off;
    const float* pF = F  + off;
    // JAX default x64-disabled: fuse_scheme materializes as int32
    const bool avg = (scheme[b] == 0);

    RowF rA[3], rB[3], rF[3];
    float sumL = 0.f, sumG = 0.f;

#pragma unroll
    for (int i = 0; i < RSTRIP + 2; ++i) {
        int y   = y0 - 1 + i;
        int cur = i % 3;
        float vA[6], vB[6], vF[6];
        load_row(pA, y, x0, vA);
        load_row(pB, y, x0, vB);
        load_row(pF, y, x0, vF);
        make_row(vA, rA[cur]);
        make_row(vB, rB[cur]);
        make_row(vF, rF[cur]);

        // l_loss contribution: rows y0 .. y0+R-1  (i in [1, R])
        if (i >= 1 && i <= RSTRIP) {
#pragma unroll
            for (int j = 0; j < 4; ++j) {
                float ab = avg ? 0.5f * (vA[j + 1] + vB[j + 1])
                               : fmaxf(vA[j + 1], vB[j + 1]);
                sumL += fabsf(ab - vF[j + 1]);
            }
        }

        // grad_loss for output row y-1 once rows y-2, y-1, y are resident
        if (i >= 2) {
            int r0 = (i - 2) % 3, r1 = (i - 1) % 3;
#pragma unroll
            for (int j = 0; j < 4; ++j) {
                float gxA = rA[r0].dh[j] + 2.f * rA[r1].dh[j] + rA[cur].dh[j];
                float gyA = rA[r0].sh[j] - rA[cur].sh[j];
                float sA  = fabsf(gxA) + fabsf(gyA);
                float gxB = rB[r0].dh[j] + 2.f * rB[r1].dh[j] + rB[cur].dh[j];
                float gyB = rB[r0].sh[j] - rB[cur].sh[j];
                float sB  = fabsf(gxB) + fabsf(gyB);
                float gxF = rF[r0].dh[j] + 2.f * rF[r1].dh[j] + rF[cur].dh[j];
                float gyF = rF[r0].sh[j] - rF[cur].sh[j];
                float sF  = fabsf(gxF) + fabsf(gyF);
                sumG += fabsf(sF - fmaxf(sA, sB));
            }
        }
    }

    // Block reduction (deterministic, no atomics)
#pragma unroll
    for (int o = 16; o > 0; o >>= 1) {
        sumL += __shfl_down_sync(0xffffffffu, sumL, o);
        sumG += __shfl_down_sync(0xffffffffu, sumG, o);
    }
    __shared__ float sL[BLOCK / 32], sG[BLOCK / 32];
    int lane = threadIdx.x & 31, wid = threadIdx.x >> 5;
    if (lane == 0) { sL[wid] = sumL; sG[wid] = sumG; }
    __syncthreads();
    if (threadIdx.x == 0) {
        float l = 0.f, g = 0.f;
#pragma unroll
        for (int k = 0; k < BLOCK / 32; ++k) { l += sL[k]; g += sG[k]; }
        g_partials[blockIdx.x] = make_float2(l, g);
    }
}

__global__ __launch_bounds__(NBLOCKS)
void fuse_finalize(float* __restrict__ out) {
    int tid = threadIdx.x;                // NBLOCKS = 512 threads
    float2 p = g_partials[tid];
    float l = p.x, g = p.y;
#pragma unroll
    for (int o = 16; o > 0; o >>= 1) {
        l += __shfl_down_sync(0xffffffffu, l, o);
        g += __shfl_down_sync(0xffffffffu, g, o);
    }
    __shared__ float sL[NBLOCKS / 32], sG[NBLOCKS / 32];
    int lane = tid & 31, wid = tid >> 5;
    if (lane == 0) { sL[wid] = l; sG[wid] = g; }
    __syncthreads();
    if (tid == 0) {
        float L = 0.f, G = 0.f;
#pragma unroll
        for (int k = 0; k < NBLOCKS / 32; ++k) { L += sL[k]; G += sG[k]; }
        out[0] = (L + G) * (1.0f / (float)NPIX);   // l_loss + grad_loss; cs_loss * 0.0 dropped
    }
}

extern "C" void kernel_launch(void* const* d_in, const int* in_sizes, int n_in,
                              void* d_out, int out_size) {
    (void)in_sizes; (void)n_in; (void)out_size;
    const float* A      = (const float*)d_in[0];
    const float* B      = (const float*)d_in[1];
    const float* F      = (const float*)d_in[2];
    const int*   scheme = (const int*)d_in[3];
    float* out = (float*)d_out;

    fuse_main<<<NBLOCKS, BLOCK>>>(A, B, F, scheme);
    fuse_finalize<<<1, NBLOCKS>>>(out);
}

// round 8
// speedup vs baseline: 1.0719x; 1.0719x over previous
#include <cuda_runtime.h>

#define IMG_W 512
#define IMG_H 512
#define NBATCH 32
#define RSTRIP 16
#define BLOCK 256
// threads: 32 batches * (512/16 y-strips) * (512/4 x-strips) = 131072
#define TOTAL_THREADS (NBATCH * (IMG_H / RSTRIP) * (IMG_W / 4))
#define NBLOCKS (TOTAL_THREADS / BLOCK)   // 512
#define NPIX ((long long)NBATCH * IMG_H * IMG_W)

__device__ float2 g_partials[NBLOCKS];
__device__ unsigned int g_ticket = 0;     // reset by the last block each call

struct RowF { float dh[4]; float sh[4]; };

__device__ __forceinline__ void load_row(const float* __restrict__ img, int y, int x0,
                                         float v[6]) {
    if ((unsigned)y < IMG_H) {
        const float* row = img + (size_t)y * IMG_W;
        float4 m = __ldg(reinterpret_cast<const float4*>(row + x0));
        v[1] = m.x; v[2] = m.y; v[3] = m.z; v[4] = m.w;
        v[0] = (x0 > 0)             ? __ldg(row + x0 - 1) : 0.f;
        v[5] = (x0 + 4 < IMG_W)     ? __ldg(row + x0 + 4) : 0.f;
    } else {
#pragma unroll
        for (int k = 0; k < 6; ++k) v[k] = 0.f;
    }
}

__device__ __forceinline__ void make_row(const float v[6], RowF& r) {
#pragma unroll
    for (int j = 0; j < 4; ++j) {
        r.dh[j] = v[j + 2] - v[j];                       // horizontal [-1,0,1]
        r.sh[j] = v[j] + 2.f * v[j + 1] + v[j + 2];      // horizontal [1,2,1]
    }
}

__global__ __launch_bounds__(BLOCK)
void fuse_main(const float* __restrict__ A, const float* __restrict__ Bi,
               const float* __restrict__ F, const int* __restrict__ scheme,
               float* __restrict__ out) {
    int t   = blockIdx.x * BLOCK + threadIdx.x;
    int b   = t >> 12;          // / 4096 strips per image
    int rem = t & 4095;
    int ys  = rem >> 7;         // 32 y-strips
    int xs  = rem & 127;        // 128 x-strips
    int x0  = xs << 2;
    int y0  = ys * RSTRIP;

    size_t off = (size_t)b * IMG_H * IMG_W;
    const float* pA = A  + off;
    const float* pB = Bi + off;
    const float* pF = F  + off;
    // JAX default x64-disabled: fuse_scheme materializes as int32
    const bool avg = (scheme[b] == 0);

    RowF rA[3], rB[3], rF[3];
    float sumL = 0.f, sumG = 0.f;

#pragma unroll
    for (int i = 0; i < RSTRIP + 2; ++i) {
        int y   = y0 - 1 + i;
        int cur = i % 3;
        float vA[6], vB[6], vF[6];
        load_row(pA, y, x0, vA);
        load_row(pB, y, x0, vB);
        load_row(pF, y, x0, vF);
        make_row(vA, rA[cur]);
        make_row(vB, rB[cur]);
        make_row(vF, rF[cur]);

        // l_loss contribution: rows y0 .. y0+R-1  (i in [1, R])
        if (i >= 1 && i <= RSTRIP) {
#pragma unroll
            for (int j = 0; j < 4; ++j) {
                float ab = avg ? 0.5f * (vA[j + 1] + vB[j + 1])
                               : fmaxf(vA[j + 1], vB[j + 1]);
                sumL += fabsf(ab - vF[j + 1]);
            }
        }

        // grad_loss for output row y-1 once rows y-2, y-1, y are resident
        if (i >= 2) {
            int r0 = (i - 2) % 3, r1 = (i - 1) % 3;
#pragma unroll
            for (int j = 0; j < 4; ++j) {
                float gxA = rA[r0].dh[j] + 2.f * rA[r1].dh[j] + rA[cur].dh[j];
                float gyA = rA[r0].sh[j] - rA[cur].sh[j];
                float sA  = fabsf(gxA) + fabsf(gyA);
                float gxB = rB[r0].dh[j] + 2.f * rB[r1].dh[j] + rB[cur].dh[j];
                float gyB = rB[r0].sh[j] - rB[cur].sh[j];
                float sB  = fabsf(gxB) + fabsf(gyB);
                float gxF = rF[r0].dh[j] + 2.f * rF[r1].dh[j] + rF[cur].dh[j];
                float gyF = rF[r0].sh[j] - rF[cur].sh[j];
                float sF  = fabsf(gxF) + fabsf(gyF);
                sumG += fabsf(sF - fmaxf(sA, sB));
            }
        }
    }

    // ---- Block reduction (deterministic, no float atomics) ----
#pragma unroll
    for (int o = 16; o > 0; o >>= 1) {
        sumL += __shfl_down_sync(0xffffffffu, sumL, o);
        sumG += __shfl_down_sync(0xffffffffu, sumG, o);
    }
    __shared__ float sL[BLOCK / 32], sG[BLOCK / 32];
    __shared__ bool s_last;
    int lane = threadIdx.x & 31, wid = threadIdx.x >> 5;
    if (lane == 0) { sL[wid] = sumL; sG[wid] = sumG; }
    __syncthreads();
    if (threadIdx.x == 0) {
        float l = 0.f, g = 0.f;
#pragma unroll
        for (int k = 0; k < BLOCK / 32; ++k) { l += sL[k]; g += sG[k]; }
        g_partials[blockIdx.x] = make_float2(l, g);
        __threadfence();
        unsigned int ticket = atomicAdd(&g_ticket, 1u);
        s_last = (ticket == NBLOCKS - 1);
    }
    __syncthreads();

    // ---- Last block finalizes: fixed-order sum over all partials ----
    if (s_last) {
        // Each thread owns NBLOCKS/BLOCK = 2 partials; order within the final
        // tree is fixed by index, so the result is bit-deterministic.
        float l = 0.f, g = 0.f;
#pragma unroll
        for (int k = 0; k < NBLOCKS / BLOCK; ++k) {
            float2 p = g_partials[threadIdx.x + k * BLOCK];
            l += p.x; g += p.y;
        }
#pragma unroll
        for (int o = 16; o > 0; o >>= 1) {
            l += __shfl_down_sync(0xffffffffu, l, o);
            g += __shfl_down_sync(0xffffffffu, g, o);
        }
        if (lane == 0) { sL[wid] = l; sG[wid] = g; }
        __syncthreads();
        if (threadIdx.x == 0) {
            float L = 0.f, G = 0.f;
#pragma unroll
            for (int k = 0; k < BLOCK / 32; ++k) { L += sL[k]; G += sG[k]; }
            out[0] = (L + G) * (1.0f / (float)NPIX);  // l_loss + grad_loss; 0.0*cs_loss dropped
            g_ticket = 0;   // reset for next graph replay (all blocks already ticketed)
        }
    }
}

extern "C" void kernel_launch(void* const* d_in, const int* in_sizes, int n_in,
                              void* d_out, int out_size) {
    (void)in_sizes; (void)n_in; (void)out_size;
    const float* A      = (const float*)d_in[0];
    const float* B      = (const float*)d_in[1];
    const float* F      = (const float*)d_in[2];
    const int*   scheme = (const int*)d_in[3];
    float* out = (float*)d_out;

    fuse_main<<<NBLOCKS, BLOCK>>>(A, B, F, scheme, out);
}